// round 1
// baseline (speedup 1.0000x reference)
#include <cuda_runtime.h>
#include <cstdint>

#define NMAX 100000
#define EMAX 1600000
#define FDIM 128
#define GMAX 64
#define CLS  10

// ---- scratch (static device allocations; no cudaMalloc allowed) ----
__device__ float g_deg [NMAX];
__device__ float g_dinv[NMAX];
__device__ float g_w   [EMAX];
__device__ float g_T1  [NMAX * FDIM];
__device__ float g_P   [NMAX * FDIM];
__device__ float g_H1  [NMAX * FDIM];
__device__ float g_H2  [NMAX * FDIM];
__device__ float g_H3  [NMAX * FDIM];
__device__ float g_sums[GMAX * FDIM];
__device__ float g_cnt [GMAX];

// ---------------------------------------------------------------
__global__ void deg_kernel(const int* __restrict__ src, int E) {
    int e = blockIdx.x * blockDim.x + threadIdx.x;
    if (e < E) atomicAdd(&g_deg[src[e]], 1.0f);
}

__global__ void dinv_kernel(int n) {
    int i = blockIdx.x * blockDim.x + threadIdx.x;
    if (i < n) {
        float d = g_deg[i];
        g_dinv[i] = (d > 0.0f) ? rsqrtf(d) : 0.0f;
    }
}

__global__ void w_kernel(const int* __restrict__ src, const int* __restrict__ dst, int E) {
    int e = blockIdx.x * blockDim.x + threadIdx.x;
    if (e < E) g_w[e] = -g_dinv[src[e]] * g_dinv[dst[e]];
}

// out[dst[e]] += w[e] * x[src[e]]   (128 floats per row, 32 lanes of float4 per edge)
__global__ void prop_kernel(const float4* __restrict__ X, float4* __restrict__ OUT,
                            const int* __restrict__ src, const int* __restrict__ dst,
                            const float* __restrict__ w, int E) {
    int idx = blockIdx.x * blockDim.x + threadIdx.x;
    if (idx >= E * 32) return;
    int e = idx >> 5;
    int c = idx & 31;
    float wv = __ldg(&w[e]);
    float4 v = __ldg(&X[(long)src[e] * 32 + c]);
    float4 r = make_float4(wv * v.x, wv * v.y, wv * v.z, wv * v.w);
    float4* p = &OUT[(long)dst[e] * 32 + c];
    asm volatile("red.global.add.v4.f32 [%0], {%1,%2,%3,%4};"
                 :: "l"(p), "f"(r.x), "f"(r.y), "f"(r.z), "f"(r.w) : "memory");
}

// OUT[i,:] = X@W0 + T1@W1 + (2P - X)@W2 + b, optional relu.
// BM=64, BN=128, BK=32; 256 threads; per-thread tile 8 rows x 4 cols.
__global__ void gemm3_kernel(const float* __restrict__ X, const float* __restrict__ T1,
                             const float* __restrict__ P,
                             const float* __restrict__ W,   // [3,128,128]
                             const float* __restrict__ b,   // [128]
                             float* __restrict__ OUT, int n, int relu) {
    __shared__ float As[64][36];     // padded: conflict-light STS, broadcast LDS
    __shared__ float Ws[32][128];

    const int tid  = threadIdx.x;
    const int trow = tid >> 5;       // 0..7  -> rows trow*8 .. trow*8+7
    const int tcol = tid & 31;       // 0..31 -> cols tcol*4 .. tcol*4+3
    const int row0 = blockIdx.x * 64;

    float acc[8][4];
#pragma unroll
    for (int r = 0; r < 8; ++r)
#pragma unroll
        for (int c = 0; c < 4; ++c) acc[r][c] = 0.0f;

    for (int s = 0; s < 3; ++s) {
        const float* A = (s == 0) ? X : (s == 1) ? T1 : P;
        for (int kb = 0; kb < 4; ++kb) {
            const int d0 = kb * 32;
            __syncthreads();
            // load A tile 64x32 (float4 per thread x2), fold T2 = 2P - X for s==2
#pragma unroll
            for (int r = 0; r < 2; ++r) {
                int q  = tid + 256 * r;      // 0..511 float4 slots
                int i  = q >> 3;             // 0..63
                int dq = (q & 7) * 4;        // 0,4,..,28
                int row = row0 + i;
                float4 v = make_float4(0.f, 0.f, 0.f, 0.f);
                if (row < n) {
                    v = __ldg((const float4*)&A[(long)row * FDIM + d0 + dq]);
                    if (s == 2) {
                        float4 u = __ldg((const float4*)&X[(long)row * FDIM + d0 + dq]);
                        v.x = 2.0f * v.x - u.x;
                        v.y = 2.0f * v.y - u.y;
                        v.z = 2.0f * v.z - u.z;
                        v.w = 2.0f * v.w - u.w;
                    }
                }
                *(float4*)&As[i][dq] = v;
            }
            // load W chunk 32x128 (float4 per thread x4)
            const float* Wsrc = W + s * (FDIM * FDIM) + d0 * FDIM;
#pragma unroll
            for (int r = 0; r < 4; ++r) {
                int q = tid + 256 * r;       // 0..1023 float4 slots
                int k = q >> 5;              // 0..31
                int j = (q & 31) * 4;
                *(float4*)&Ws[k][j] = __ldg((const float4*)&Wsrc[k * FDIM + j]);
            }
            __syncthreads();
#pragma unroll
            for (int kk = 0; kk < 32; ++kk) {
                float a[8];
#pragma unroll
                for (int rr = 0; rr < 8; ++rr) a[rr] = As[trow * 8 + rr][kk];
                float4 wv = *(float4*)&Ws[kk][tcol * 4];
#pragma unroll
                for (int rr = 0; rr < 8; ++rr) {
                    acc[rr][0] = fmaf(a[rr], wv.x, acc[rr][0]);
                    acc[rr][1] = fmaf(a[rr], wv.y, acc[rr][1]);
                    acc[rr][2] = fmaf(a[rr], wv.z, acc[rr][2]);
                    acc[rr][3] = fmaf(a[rr], wv.w, acc[rr][3]);
                }
            }
        }
    }

    float4 bv = __ldg((const float4*)&b[tcol * 4]);
#pragma unroll
    for (int rr = 0; rr < 8; ++rr) {
        int row = row0 + trow * 8 + rr;
        if (row < n) {
            float4 o;
            o.x = acc[rr][0] + bv.x;
            o.y = acc[rr][1] + bv.y;
            o.z = acc[rr][2] + bv.z;
            o.w = acc[rr][3] + bv.w;
            if (relu) {
                o.x = fmaxf(o.x, 0.f); o.y = fmaxf(o.y, 0.f);
                o.z = fmaxf(o.z, 0.f); o.w = fmaxf(o.w, 0.f);
            }
            *(float4*)&OUT[(long)row * FDIM + tcol * 4] = o;
        }
    }
}

__global__ void cnt_kernel(const int* __restrict__ batch, int n) {
    int i = blockIdx.x * blockDim.x + threadIdx.x;
    if (i < n) atomicAdd(&g_cnt[batch[i]], 1.0f);
}

__global__ void pool_kernel(const float4* __restrict__ H, const int* __restrict__ batch, int n) {
    int idx = blockIdx.x * blockDim.x + threadIdx.x;
    if (idx >= n * 32) return;
    int row = idx >> 5;
    int c   = idx & 31;
    int g   = batch[row];
    float4 v = __ldg(&H[(long)row * 32 + c]);
    float4* p = (float4*)&g_sums[g * FDIM + c * 4];
    asm volatile("red.global.add.v4.f32 [%0], {%1,%2,%3,%4};"
                 :: "l"(p), "f"(v.x), "f"(v.y), "f"(v.z), "f"(v.w) : "memory");
}

__global__ void final_kernel(const float* __restrict__ Wl, const float* __restrict__ bl,
                             float* __restrict__ out, int ngraphs) {
    int tid = blockIdx.x * blockDim.x + threadIdx.x;
    if (tid >= ngraphs * CLS) return;
    int g = tid / CLS;
    int c = tid % CLS;
    float s = 0.0f;
    const float* sp = &g_sums[g * FDIM];
#pragma unroll 16
    for (int d = 0; d < FDIM; ++d) s = fmaf(sp[d], Wl[d * CLS + c], s);
    float cnt = fmaxf(g_cnt[g], 1.0f);
    out[g * CLS + c] = s / cnt + bl[c];
}

// ---------------------------------------------------------------
extern "C" void kernel_launch(void* const* d_in, const int* in_sizes, int n_in,
                              void* d_out, int out_size) {
    const float* x   = (const float*)d_in[0];
    const int*   ei  = (const int*)  d_in[1];
    const int*   bat = (const int*)  d_in[2];
    const float* W1  = (const float*)d_in[3];
    const float* b1  = (const float*)d_in[4];
    const float* W2  = (const float*)d_in[5];
    const float* b2  = (const float*)d_in[6];
    const float* W3  = (const float*)d_in[7];
    const float* b3  = (const float*)d_in[8];
    const float* Wl  = (const float*)d_in[9];
    const float* bl  = (const float*)d_in[10];
    float* out = (float*)d_out;

    const int n = in_sizes[0] / FDIM;          // 100000
    const int E = in_sizes[1] / 2;             // 1600000
    const int G = out_size / CLS;              // 64
    const int* src = ei;
    const int* dst = ei + E;

    float *deg, *T1, *P, *H1, *H2, *H3, *sums, *cnt, *wgt, *dinv;
    cudaGetSymbolAddress((void**)&deg,  g_deg);
    cudaGetSymbolAddress((void**)&dinv, g_dinv);
    cudaGetSymbolAddress((void**)&wgt,  g_w);
    cudaGetSymbolAddress((void**)&T1,   g_T1);
    cudaGetSymbolAddress((void**)&P,    g_P);
    cudaGetSymbolAddress((void**)&H1,   g_H1);
    cudaGetSymbolAddress((void**)&H2,   g_H2);
    cudaGetSymbolAddress((void**)&H3,   g_H3);
    cudaGetSymbolAddress((void**)&sums, g_sums);
    cudaGetSymbolAddress((void**)&cnt,  g_cnt);

    const int TB = 256;
    const size_t featBytes = (size_t)n * FDIM * sizeof(float);

    // degrees + normalized edge weights
    cudaMemsetAsync(deg, 0, (size_t)n * sizeof(float));
    deg_kernel <<<(E + TB - 1) / TB, TB>>>(src, E);
    dinv_kernel<<<(n + TB - 1) / TB, TB>>>(n);
    w_kernel   <<<(E + TB - 1) / TB, TB>>>(src, dst, E);

    const int propBlocks = (E * 32 + TB - 1) / TB;
    const int gemmBlocks = (n + 63) / 64;

    struct Layer { const float* X; const float* W; const float* b; float* O; int relu; };
    Layer layers[3] = {
        { x,  W1, b1, H1, 1 },
        { H1, W2, b2, H2, 1 },
        { H2, W3, b3, H3, 0 },
    };

    for (int l = 0; l < 3; ++l) {
        const float* X = layers[l].X;
        cudaMemsetAsync(T1, 0, featBytes);
        prop_kernel<<<propBlocks, TB>>>((const float4*)X, (float4*)T1, src, dst, wgt, E);
        cudaMemsetAsync(P, 0, featBytes);
        prop_kernel<<<propBlocks, TB>>>((const float4*)T1, (float4*)P, src, dst, wgt, E);
        gemm3_kernel<<<gemmBlocks, TB>>>(X, T1, P, layers[l].W, layers[l].b,
                                         layers[l].O, n, layers[l].relu);
    }

    // mean pool + classifier
    cudaMemsetAsync(sums, 0, (size_t)G * FDIM * sizeof(float));
    cudaMemsetAsync(cnt,  0, (size_t)G * sizeof(float));
    cnt_kernel <<<(n + TB - 1) / TB, TB>>>(bat, n);
    pool_kernel<<<(n * 32 + TB - 1) / TB, TB>>>((const float4*)H3, bat, n);
    final_kernel<<<(G * CLS + TB - 1) / TB, TB>>>(Wl, bl, out, G);
}

// round 2
// speedup vs baseline: 1.6597x; 1.6597x over previous
#include <cuda_runtime.h>
#include <cstdint>

#define NMAX 100000
#define EMAX 1600000
#define FDIM 128
#define GMAX 64
#define CLS  10
#define SCAN_B 1024

// ---- scratch (static device arrays; no cudaMalloc allowed) ----
__device__ float g_deg    [NMAX];
__device__ float g_dinv   [NMAX];
__device__ int   g_rcnt   [NMAX];        // per-dst edge counts
__device__ int   g_incl   [NMAX];        // inclusive scan within blocks
__device__ int   g_part   [256];         // per-block partial sums
__device__ int   g_rowptr [NMAX + 1];
__device__ int   g_fill   [NMAX];
__device__ int   g_csrsrc [EMAX];
__device__ float g_csrw   [EMAX];
__device__ float g_T1  [NMAX * FDIM];
__device__ float g_P   [NMAX * FDIM];
__device__ float g_H1  [NMAX * FDIM];
__device__ float g_H2  [NMAX * FDIM];
__device__ float g_H3  [NMAX * FDIM];
__device__ float g_sums[GMAX * FDIM];
__device__ float g_cnt [GMAX];

// ---------------- packed f32x2 helpers ----------------
__device__ __forceinline__ unsigned long long pack2(float x, float y) {
    unsigned long long r;
    asm("mov.b64 %0, {%1, %2};" : "=l"(r) : "f"(x), "f"(y));
    return r;
}
__device__ __forceinline__ void unpack2(unsigned long long v, float& lo, float& hi) {
    asm("mov.b64 {%0, %1}, %2;" : "=f"(lo), "=f"(hi) : "l"(v));
}
__device__ __forceinline__ unsigned long long fma2(unsigned long long a,
                                                   unsigned long long b,
                                                   unsigned long long c) {
    unsigned long long d;
    asm("fma.rn.f32x2 %0, %1, %2, %3;" : "=l"(d) : "l"(a), "l"(b), "l"(c));
    return d;
}

// ---------------- norm prepass ----------------
__global__ void deg_kernel(const int* __restrict__ src, int E) {
    int e = blockIdx.x * blockDim.x + threadIdx.x;
    if (e < E) atomicAdd(&g_deg[src[e]], 1.0f);
}
__global__ void dinv_kernel(int n) {
    int i = blockIdx.x * blockDim.x + threadIdx.x;
    if (i < n) {
        float d = g_deg[i];
        g_dinv[i] = (d > 0.0f) ? rsqrtf(d) : 0.0f;
    }
}

// ---------------- CSR build (by dst) ----------------
__global__ void rcnt_kernel(const int* __restrict__ dst, int E) {
    int e = blockIdx.x * blockDim.x + threadIdx.x;
    if (e < E) atomicAdd(&g_rcnt[dst[e]], 1);
}
__global__ void scan1_kernel(int n) {
    __shared__ int sm[SCAN_B];
    int i = blockIdx.x * SCAN_B + threadIdx.x;
    int v = (i < n) ? g_rcnt[i] : 0;
    sm[threadIdx.x] = v;
    __syncthreads();
    for (int off = 1; off < SCAN_B; off <<= 1) {
        int t = (threadIdx.x >= off) ? sm[threadIdx.x - off] : 0;
        __syncthreads();
        sm[threadIdx.x] += t;
        __syncthreads();
    }
    if (i < n) g_incl[i] = sm[threadIdx.x];
    if (threadIdx.x == SCAN_B - 1) g_part[blockIdx.x] = sm[threadIdx.x];
}
__global__ void scan2_kernel(int nb) {   // one block, 256 threads, exclusive scan
    __shared__ int sm[256];
    int v = (threadIdx.x < nb) ? g_part[threadIdx.x] : 0;
    sm[threadIdx.x] = v;
    __syncthreads();
    for (int off = 1; off < 256; off <<= 1) {
        int t = (threadIdx.x >= off) ? sm[threadIdx.x - off] : 0;
        __syncthreads();
        sm[threadIdx.x] += t;
        __syncthreads();
    }
    if (threadIdx.x < nb) g_part[threadIdx.x] = sm[threadIdx.x] - v;
}
__global__ void scan3_kernel(int n) {
    int i = blockIdx.x * blockDim.x + threadIdx.x;
    if (i < n) g_rowptr[i + 1] = g_incl[i] + g_part[i / SCAN_B];
    if (i == 0) g_rowptr[0] = 0;
}
__global__ void fill_kernel(const int* __restrict__ src, const int* __restrict__ dst, int E) {
    int e = blockIdx.x * blockDim.x + threadIdx.x;
    if (e >= E) return;
    int d = dst[e], s = src[e];
    int p = g_rowptr[d] + atomicAdd(&g_fill[d], 1);
    g_csrsrc[p] = s;
    g_csrw[p]   = -g_dinv[s] * g_dinv[d];
}

// ---------------- CSR propagation: one warp per output row ----------------
__global__ void prop_csr_kernel(const float4* __restrict__ X, float4* __restrict__ OUT, int n) {
    int gw   = (blockIdx.x * blockDim.x + threadIdx.x) >> 5;
    if (gw >= n) return;
    int lane = threadIdx.x & 31;
    int p    = __ldg(&g_rowptr[gw]);
    int end  = __ldg(&g_rowptr[gw + 1]);
    float4 acc = make_float4(0.f, 0.f, 0.f, 0.f);
    // 4-way unrolled gather for MLP
    for (; p + 3 < end; p += 4) {
        int   s0 = __ldg(&g_csrsrc[p]),   s1 = __ldg(&g_csrsrc[p+1]);
        int   s2 = __ldg(&g_csrsrc[p+2]), s3 = __ldg(&g_csrsrc[p+3]);
        float w0 = __ldg(&g_csrw[p]),     w1 = __ldg(&g_csrw[p+1]);
        float w2 = __ldg(&g_csrw[p+2]),   w3 = __ldg(&g_csrw[p+3]);
        float4 v0 = __ldg(&X[(long)s0 * 32 + lane]);
        float4 v1 = __ldg(&X[(long)s1 * 32 + lane]);
        float4 v2 = __ldg(&X[(long)s2 * 32 + lane]);
        float4 v3 = __ldg(&X[(long)s3 * 32 + lane]);
        acc.x += w0*v0.x + w1*v1.x + w2*v2.x + w3*v3.x;
        acc.y += w0*v0.y + w1*v1.y + w2*v2.y + w3*v3.y;
        acc.z += w0*v0.z + w1*v1.z + w2*v2.z + w3*v3.z;
        acc.w += w0*v0.w + w1*v1.w + w2*v2.w + w3*v3.w;
    }
    for (; p < end; ++p) {
        int   s = __ldg(&g_csrsrc[p]);
        float w = __ldg(&g_csrw[p]);
        float4 v = __ldg(&X[(long)s * 32 + lane]);
        acc.x += w*v.x; acc.y += w*v.y; acc.z += w*v.z; acc.w += w*v.w;
    }
    OUT[(long)gw * 32 + lane] = acc;
}

// ---------------- fused 3-term GEMM with packed f32x2 FMA ----------------
// OUT[i,:] = X@W0 + T1@W1 + (2P - X)@W2 + b, optional relu.
// BM=64, BN=128, BK=32; 256 threads; per-thread: 4 row-pairs x 4 cols.
__global__ void gemm3_kernel(const float* __restrict__ X, const float* __restrict__ T1,
                             const float* __restrict__ P,
                             const float* __restrict__ W,   // [3,128,128]
                             const float* __restrict__ b,   // [128]
                             float* __restrict__ OUT, int n, int relu) {
    __shared__ float Ask[32][66];    // A tile transposed: [k][row], padded
    __shared__ float Ws[32][128];

    const int tid  = threadIdx.x;
    const int trow = tid >> 5;       // warp id: rows trow*8 .. trow*8+7
    const int tcol = tid & 31;       // cols tcol*4 .. tcol*4+3
    const int row0 = blockIdx.x * 64;

    unsigned long long acc[4][4];    // [rowpair][col], each packs (row 2rp, 2rp+1)
#pragma unroll
    for (int rp = 0; rp < 4; ++rp)
#pragma unroll
        for (int c = 0; c < 4; ++c) acc[rp][c] = 0ull;

    for (int s = 0; s < 3; ++s) {
        const float* A = (s == 0) ? X : (s == 1) ? T1 : P;
        for (int kb = 0; kb < 4; ++kb) {
            const int d0 = kb * 32;
            __syncthreads();
            // A tile 64 rows x 32 k, stored transposed
#pragma unroll
            for (int r = 0; r < 2; ++r) {
                int q  = tid + 256 * r;      // 0..511 float4 slots
                int i  = q >> 3;             // row in tile 0..63
                int dq = (q & 7) * 4;        // k offset 0,4,..,28
                int row = row0 + i;
                float4 v = make_float4(0.f, 0.f, 0.f, 0.f);
                if (row < n) {
                    v = __ldg((const float4*)&A[(long)row * FDIM + d0 + dq]);
                    if (s == 2) {
                        float4 u = __ldg((const float4*)&X[(long)row * FDIM + d0 + dq]);
                        v.x = 2.0f * v.x - u.x;
                        v.y = 2.0f * v.y - u.y;
                        v.z = 2.0f * v.z - u.z;
                        v.w = 2.0f * v.w - u.w;
                    }
                }
                Ask[dq + 0][i] = v.x;
                Ask[dq + 1][i] = v.y;
                Ask[dq + 2][i] = v.z;
                Ask[dq + 3][i] = v.w;
            }
            // W chunk 32x128
            const float* Wsrc = W + s * (FDIM * FDIM) + d0 * FDIM;
#pragma unroll
            for (int r = 0; r < 4; ++r) {
                int q = tid + 256 * r;
                int k = q >> 5;
                int j = (q & 31) * 4;
                *(float4*)&Ws[k][j] = __ldg((const float4*)&Wsrc[k * FDIM + j]);
            }
            __syncthreads();
#pragma unroll
            for (int kk = 0; kk < 32; ++kk) {
                // broadcast row-pair loads (all lanes same address)
                unsigned long long a0 = *(const unsigned long long*)&Ask[kk][trow * 8 + 0];
                unsigned long long a1 = *(const unsigned long long*)&Ask[kk][trow * 8 + 2];
                unsigned long long a2 = *(const unsigned long long*)&Ask[kk][trow * 8 + 4];
                unsigned long long a3 = *(const unsigned long long*)&Ask[kk][trow * 8 + 6];
                float4 wv = *(const float4*)&Ws[kk][tcol * 4];
                unsigned long long w0 = pack2(wv.x, wv.x);
                unsigned long long w1 = pack2(wv.y, wv.y);
                unsigned long long w2 = pack2(wv.z, wv.z);
                unsigned long long w3 = pack2(wv.w, wv.w);
                acc[0][0] = fma2(a0, w0, acc[0][0]);
                acc[0][1] = fma2(a0, w1, acc[0][1]);
                acc[0][2] = fma2(a0, w2, acc[0][2]);
                acc[0][3] = fma2(a0, w3, acc[0][3]);
                acc[1][0] = fma2(a1, w0, acc[1][0]);
                acc[1][1] = fma2(a1, w1, acc[1][1]);
                acc[1][2] = fma2(a1, w2, acc[1][2]);
                acc[1][3] = fma2(a1, w3, acc[1][3]);
                acc[2][0] = fma2(a2, w0, acc[2][0]);
                acc[2][1] = fma2(a2, w1, acc[2][1]);
                acc[2][2] = fma2(a2, w2, acc[2][2]);
                acc[2][3] = fma2(a2, w3, acc[2][3]);
                acc[3][0] = fma2(a3, w0, acc[3][0]);
                acc[3][1] = fma2(a3, w1, acc[3][1]);
                acc[3][2] = fma2(a3, w2, acc[3][2]);
                acc[3][3] = fma2(a3, w3, acc[3][3]);
            }
        }
    }

    float4 bv = __ldg((const float4*)&b[tcol * 4]);
#pragma unroll
    for (int rp = 0; rp < 4; ++rp) {
        float lo0, hi0, lo1, hi1, lo2, hi2, lo3, hi3;
        unpack2(acc[rp][0], lo0, hi0);
        unpack2(acc[rp][1], lo1, hi1);
        unpack2(acc[rp][2], lo2, hi2);
        unpack2(acc[rp][3], lo3, hi3);
        float4 oe = make_float4(lo0 + bv.x, lo1 + bv.y, lo2 + bv.z, lo3 + bv.w);
        float4 oo = make_float4(hi0 + bv.x, hi1 + bv.y, hi2 + bv.z, hi3 + bv.w);
        if (relu) {
            oe.x = fmaxf(oe.x, 0.f); oe.y = fmaxf(oe.y, 0.f);
            oe.z = fmaxf(oe.z, 0.f); oe.w = fmaxf(oe.w, 0.f);
            oo.x = fmaxf(oo.x, 0.f); oo.y = fmaxf(oo.y, 0.f);
            oo.z = fmaxf(oo.z, 0.f); oo.w = fmaxf(oo.w, 0.f);
        }
        int re = row0 + trow * 8 + 2 * rp;
        int ro = re + 1;
        if (re < n) *(float4*)&OUT[(long)re * FDIM + tcol * 4] = oe;
        if (ro < n) *(float4*)&OUT[(long)ro * FDIM + tcol * 4] = oo;
    }
}

// ---------------- pooling + classifier ----------------
__global__ void cnt_kernel(const int* __restrict__ batch, int n) {
    int i = blockIdx.x * blockDim.x + threadIdx.x;
    if (i < n) atomicAdd(&g_cnt[batch[i]], 1.0f);
}
__global__ void pool_kernel(const float4* __restrict__ H, const int* __restrict__ batch, int n) {
    int idx = blockIdx.x * blockDim.x + threadIdx.x;
    if (idx >= n * 32) return;
    int row = idx >> 5;
    int c   = idx & 31;
    int g   = batch[row];
    float4 v = __ldg(&H[(long)row * 32 + c]);
    float4* p = (float4*)&g_sums[g * FDIM + c * 4];
    asm volatile("red.global.add.v4.f32 [%0], {%1,%2,%3,%4};"
                 :: "l"(p), "f"(v.x), "f"(v.y), "f"(v.z), "f"(v.w) : "memory");
}
__global__ void final_kernel(const float* __restrict__ Wl, const float* __restrict__ bl,
                             float* __restrict__ out, int ngraphs) {
    int tid = blockIdx.x * blockDim.x + threadIdx.x;
    if (tid >= ngraphs * CLS) return;
    int g = tid / CLS;
    int c = tid % CLS;
    float s = 0.0f;
    const float* sp = &g_sums[g * FDIM];
#pragma unroll 16
    for (int d = 0; d < FDIM; ++d) s = fmaf(sp[d], Wl[d * CLS + c], s);
    float cnt = fmaxf(g_cnt[g], 1.0f);
    out[g * CLS + c] = s / cnt + bl[c];
}

// ---------------------------------------------------------------
extern "C" void kernel_launch(void* const* d_in, const int* in_sizes, int n_in,
                              void* d_out, int out_size) {
    const float* x   = (const float*)d_in[0];
    const int*   ei  = (const int*)  d_in[1];
    const int*   bat = (const int*)  d_in[2];
    const float* W1  = (const float*)d_in[3];
    const float* b1  = (const float*)d_in[4];
    const float* W2  = (const float*)d_in[5];
    const float* b2  = (const float*)d_in[6];
    const float* W3  = (const float*)d_in[7];
    const float* b3  = (const float*)d_in[8];
    const float* Wl  = (const float*)d_in[9];
    const float* bl  = (const float*)d_in[10];
    float* out = (float*)d_out;

    const int n = in_sizes[0] / FDIM;          // 100000
    const int E = in_sizes[1] / 2;             // 1600000
    const int G = out_size / CLS;              // 64
    const int* src = ei;
    const int* dst = ei + E;

    float *deg, *T1, *P, *H1, *H2, *H3, *sums, *cnt;
    int *rcnt, *fill;
    cudaGetSymbolAddress((void**)&deg,  g_deg);
    cudaGetSymbolAddress((void**)&rcnt, g_rcnt);
    cudaGetSymbolAddress((void**)&fill, g_fill);
    cudaGetSymbolAddress((void**)&T1,   g_T1);
    cudaGetSymbolAddress((void**)&P,    g_P);
    cudaGetSymbolAddress((void**)&H1,   g_H1);
    cudaGetSymbolAddress((void**)&H2,   g_H2);
    cudaGetSymbolAddress((void**)&H3,   g_H3);
    cudaGetSymbolAddress((void**)&sums, g_sums);
    cudaGetSymbolAddress((void**)&cnt,  g_cnt);

    const int TB = 256;

    // degree / normalization
    cudaMemsetAsync(deg, 0, (size_t)n * sizeof(float));
    deg_kernel <<<(E + TB - 1) / TB, TB>>>(src, E);
    dinv_kernel<<<(n + TB - 1) / TB, TB>>>(n);

    // CSR build (by dst)
    cudaMemsetAsync(rcnt, 0, (size_t)n * sizeof(int));
    cudaMemsetAsync(fill, 0, (size_t)n * sizeof(int));
    rcnt_kernel<<<(E + TB - 1) / TB, TB>>>(dst, E);
    const int nb = (n + SCAN_B - 1) / SCAN_B;
    scan1_kernel<<<nb, SCAN_B>>>(n);
    scan2_kernel<<<1, 256>>>(nb);
    scan3_kernel<<<(n + TB - 1) / TB, TB>>>(n);
    fill_kernel<<<(E + TB - 1) / TB, TB>>>(src, dst, E);

    const int propBlocks = (n * 32 + TB - 1) / TB;
    const int gemmBlocks = (n + 63) / 64;

    struct Layer { const float* X; const float* W; const float* b; float* O; int relu; };
    Layer layers[3] = {
        { x,  W1, b1, H1, 1 },
        { H1, W2, b2, H2, 1 },
        { H2, W3, b3, H3, 0 },
    };

    for (int l = 0; l < 3; ++l) {
        const float* X = layers[l].X;
        prop_csr_kernel<<<propBlocks, TB>>>((const float4*)X, (float4*)T1, n);
        prop_csr_kernel<<<propBlocks, TB>>>((const float4*)T1, (float4*)P, n);
        gemm3_kernel<<<gemmBlocks, TB>>>(X, T1, P, layers[l].W, layers[l].b,
                                         layers[l].O, n, layers[l].relu);
    }

    // mean pool + classifier
    cudaMemsetAsync(sums, 0, (size_t)G * FDIM * sizeof(float));
    cudaMemsetAsync(cnt,  0, (size_t)G * sizeof(float));
    cnt_kernel <<<(n + TB - 1) / TB, TB>>>(bat, n);
    pool_kernel<<<(n * 32 + TB - 1) / TB, TB>>>((const float4*)H3, bat, n);
    final_kernel<<<(G * CLS + TB - 1) / TB, TB>>>(Wl, bl, out, G);
}

// round 5
// speedup vs baseline: 1.8623x; 1.1221x over previous
#include <cuda_runtime.h>
#include <cuda_bf16.h>
#include <cstdint>

#define NMAX 100000
#define EMAX 1600000
#define FDIM 128
#define GMAX 64
#define CLS  10
#define SCAN_B 1024

// ---- scratch (static device arrays; no cudaMalloc allowed) ----
__device__ float g_deg    [NMAX];
__device__ float g_dinv   [NMAX];
__device__ int   g_rcnt   [NMAX];
__device__ int   g_incl   [NMAX];
__device__ int   g_part   [256];
__device__ int   g_rowptr [NMAX + 1];
__device__ int   g_fill   [NMAX];
__device__ int   g_csrsrc [EMAX];
__device__ float g_csrw   [EMAX];
__device__ float g_T1  [NMAX * FDIM];
__device__ float g_T2  [NMAX * FDIM];
__device__ float g_H1  [NMAX * FDIM];
__device__ float g_H2  [NMAX * FDIM];
__device__ float g_H3  [NMAX * FDIM];
__device__ float g_sums[GMAX * FDIM];
__device__ float g_cnt [GMAX];
// pre-converted weights, k-interleaved layout, padded rows (136 bf16 per n-row):
// per layer: [src 0..2][ hi: 128*136 | lo: 128*136 ]  -> 34816 bf16 per src
__device__ __nv_bfloat16 g_Wc[3 * 3 * 34816];

// bf16-pair position of even k within a padded 136-elem row:
// group g = k>>4 (16 elems), pair p = (k>>1)&7; chunk order (0,4),(1,5),(2,6),(3,7)
__host__ __device__ __forceinline__ int kpos_even(int k) {
    int p = (k >> 1) & 7;
    return (k >> 4) * 16 + ((p & 3) << 2) + ((p >> 2) << 1);
}

// ================= norm prepass =================
__global__ void deg_kernel(const int* __restrict__ src, int E) {
    int e = blockIdx.x * blockDim.x + threadIdx.x;
    if (e < E) atomicAdd(&g_deg[src[e]], 1.0f);
}
__global__ void dinv_kernel(int n) {
    int i = blockIdx.x * blockDim.x + threadIdx.x;
    if (i < n) {
        float d = g_deg[i];
        g_dinv[i] = (d > 0.0f) ? rsqrtf(d) : 0.0f;
    }
}

// ================= CSR build (by dst) =================
__global__ void rcnt_kernel(const int* __restrict__ dst, int E) {
    int e = blockIdx.x * blockDim.x + threadIdx.x;
    if (e < E) atomicAdd(&g_rcnt[dst[e]], 1);
}
__global__ void scan1_kernel(int n) {
    __shared__ int sm[SCAN_B];
    int i = blockIdx.x * SCAN_B + threadIdx.x;
    int v = (i < n) ? g_rcnt[i] : 0;
    sm[threadIdx.x] = v;
    __syncthreads();
    for (int off = 1; off < SCAN_B; off <<= 1) {
        int t = (threadIdx.x >= off) ? sm[threadIdx.x - off] : 0;
        __syncthreads();
        sm[threadIdx.x] += t;
        __syncthreads();
    }
    if (i < n) g_incl[i] = sm[threadIdx.x];
    if (threadIdx.x == SCAN_B - 1) g_part[blockIdx.x] = sm[threadIdx.x];
}
__global__ void scan2_kernel(int nb) {
    __shared__ int sm[256];
    int v = (threadIdx.x < nb) ? g_part[threadIdx.x] : 0;
    sm[threadIdx.x] = v;
    __syncthreads();
    for (int off = 1; off < 256; off <<= 1) {
        int t = (threadIdx.x >= off) ? sm[threadIdx.x - off] : 0;
        __syncthreads();
        sm[threadIdx.x] += t;
        __syncthreads();
    }
    if (threadIdx.x < nb) g_part[threadIdx.x] = sm[threadIdx.x] - v;
}
__global__ void scan3_kernel(int n) {
    int i = blockIdx.x * blockDim.x + threadIdx.x;
    if (i < n) g_rowptr[i + 1] = g_incl[i] + g_part[i / SCAN_B];
    if (i == 0) g_rowptr[0] = 0;
}
__global__ void fill_kernel(const int* __restrict__ src, const int* __restrict__ dst, int E) {
    int e = blockIdx.x * blockDim.x + threadIdx.x;
    if (e >= E) return;
    int d = dst[e], s = src[e];
    int p = g_rowptr[d] + atomicAdd(&g_fill[d], 1);
    g_csrsrc[p] = s;
    g_csrw[p]   = -g_dinv[s] * g_dinv[d];
}

// ================= CSR propagation: one warp per output row =================
// mode 0: OUT = Lhat*X ; mode 1: OUT = 2*(Lhat*X) - X0
template <int MODE>
__global__ void prop_csr_kernel(const float4* __restrict__ X, const float4* __restrict__ X0,
                                float4* __restrict__ OUT, int n) {
    int gw   = (blockIdx.x * blockDim.x + threadIdx.x) >> 5;
    if (gw >= n) return;
    int lane = threadIdx.x & 31;
    int p    = __ldg(&g_rowptr[gw]);
    int end  = __ldg(&g_rowptr[gw + 1]);
    float4 acc = make_float4(0.f, 0.f, 0.f, 0.f);
    for (; p + 3 < end; p += 4) {
        int   s0 = __ldg(&g_csrsrc[p]),   s1 = __ldg(&g_csrsrc[p+1]);
        int   s2 = __ldg(&g_csrsrc[p+2]), s3 = __ldg(&g_csrsrc[p+3]);
        float w0 = __ldg(&g_csrw[p]),     w1 = __ldg(&g_csrw[p+1]);
        float w2 = __ldg(&g_csrw[p+2]),   w3 = __ldg(&g_csrw[p+3]);
        float4 v0 = __ldg(&X[(long)s0 * 32 + lane]);
        float4 v1 = __ldg(&X[(long)s1 * 32 + lane]);
        float4 v2 = __ldg(&X[(long)s2 * 32 + lane]);
        float4 v3 = __ldg(&X[(long)s3 * 32 + lane]);
        acc.x += w0*v0.x + w1*v1.x + w2*v2.x + w3*v3.x;
        acc.y += w0*v0.y + w1*v1.y + w2*v2.y + w3*v3.y;
        acc.z += w0*v0.z + w1*v1.z + w2*v2.z + w3*v3.z;
        acc.w += w0*v0.w + w1*v1.w + w2*v2.w + w3*v3.w;
    }
    for (; p < end; ++p) {
        int   s = __ldg(&g_csrsrc[p]);
        float w = __ldg(&g_csrw[p]);
        float4 v = __ldg(&X[(long)s * 32 + lane]);
        acc.x += w*v.x; acc.y += w*v.y; acc.z += w*v.z; acc.w += w*v.w;
    }
    if (MODE == 1) {
        float4 u = __ldg(&X0[(long)gw * 32 + lane]);
        acc.x = 2.f * acc.x - u.x; acc.y = 2.f * acc.y - u.y;
        acc.z = 2.f * acc.z - u.z; acc.w = 2.f * acc.w - u.w;
    }
    OUT[(long)gw * 32 + lane] = acc;
}

// ================= weight pre-conversion =================
// W[s][k][n] fp32 -> k-interleaved bf16 hi/lo, row pitch 136, per metadata above.
__global__ void wcvt_kernel(const float* __restrict__ W, __nv_bfloat16* __restrict__ out) {
    int e = blockIdx.x * blockDim.x + threadIdx.x;
    if (e >= 3 * 16384) return;
    int s   = e >> 14;
    int r   = e & 16383;
    int k   = r >> 7;
    int nn  = r & 127;
    float v = W[s * 16384 + (size_t)k * 128 + nn];
    __nv_bfloat16 h = __float2bfloat16(v);
    __nv_bfloat16 l = __float2bfloat16(v - __bfloat162float(h));
    int pos = kpos_even(k & ~1) + (k & 1);
    __nv_bfloat16* o = out + (size_t)s * 34816 + nn * 136 + pos;
    o[0]     = h;
    o[17408] = l;
}

// ================= bf16 mma.sync GEMM =================
// OUT = X@W0 + T1@W1 + T2@W2 + b (relu optional), split-precision 3-pass bf16.
// Block 256 thr = 8 warps (4M x 2N); BM=BN=128; warp tile 32x64.
#define APITCH 272      // bytes per A/W row (136 bf16)
#define SMA_HI 0
#define SMA_LO (128 * APITCH)
#define SMW_HI (2 * 128 * APITCH)
#define SMW_LO (3 * 128 * APITCH)
#define SM_GEMM (4 * 128 * APITCH)    // 139264 B

__device__ __forceinline__ void mma_bf16(float& d0, float& d1, float& d2, float& d3,
                                         uint32_t a0, uint32_t a1, uint32_t a2, uint32_t a3,
                                         uint32_t b0, uint32_t b1) {
    asm volatile("mma.sync.aligned.m16n8k16.row.col.f32.bf16.bf16.f32 "
                 "{%0,%1,%2,%3}, {%4,%5,%6,%7}, {%8,%9}, {%0,%1,%2,%3};"
                 : "+f"(d0), "+f"(d1), "+f"(d2), "+f"(d3)
                 : "r"(a0), "r"(a1), "r"(a2), "r"(a3), "r"(b0), "r"(b1));
}

__global__ void __launch_bounds__(256, 1) gemm_mma_kernel(
    const float* __restrict__ S0, const float* __restrict__ S1, const float* __restrict__ S2,
    const __nv_bfloat16* __restrict__ Wc, const float* __restrict__ bias,
    float* __restrict__ OUT, int n, int relu)
{
    extern __shared__ __align__(16) char smem[];
    const int tid  = threadIdx.x;
    const int wid  = tid >> 5;
    const int lane = tid & 31;
    const int wm   = wid & 3;          // 0..3 -> rows wm*32
    const int wn   = wid >> 2;         // 0..1 -> cols wn*64
    const int row0 = blockIdx.x * 128;

    float acc[2][8][4];
#pragma unroll
    for (int i = 0; i < 2; ++i)
#pragma unroll
        for (int j = 0; j < 8; ++j)
#pragma unroll
            for (int c = 0; c < 4; ++c) acc[i][j][c] = 0.0f;

    const int srow = tid >> 1;            // staging row 0..127
    const int kbase = (tid & 1) * 64;     // staging k half

    for (int s = 0; s < 3; ++s) {
        const float* A = (s == 0) ? S0 : (s == 1) ? S1 : S2;
        __syncthreads();
        // ---- stage A (fp32 -> bf16 hi/lo, k-interleaved) ----
        {
            uint32_t* ah = (uint32_t*)(smem + SMA_HI + srow * APITCH);
            uint32_t* al = (uint32_t*)(smem + SMA_LO + srow * APITCH);
            const int rg = row0 + srow;
            const float4* arow = (const float4*)(A + (size_t)rg * FDIM + kbase);
#pragma unroll 4
            for (int j = 0; j < 16; ++j) {
                float4 v = (rg < n) ? __ldg(&arow[j]) : make_float4(0.f, 0.f, 0.f, 0.f);
                int k0 = kbase + 4 * j;
                __nv_bfloat16 h0 = __float2bfloat16(v.x), h1 = __float2bfloat16(v.y);
                __nv_bfloat16 h2 = __float2bfloat16(v.z), h3 = __float2bfloat16(v.w);
                __nv_bfloat16 l0 = __float2bfloat16(v.x - __bfloat162float(h0));
                __nv_bfloat16 l1 = __float2bfloat16(v.y - __bfloat162float(h1));
                __nv_bfloat16 l2 = __float2bfloat16(v.z - __bfloat162float(h2));
                __nv_bfloat16 l3 = __float2bfloat16(v.w - __bfloat162float(h3));
                int wA = kpos_even(k0) >> 1;
                int wB = kpos_even(k0 + 2) >> 1;
                union { __nv_bfloat162 b; uint32_t u; } t;
                t.b = __halves2bfloat162(h0, h1); ah[wA] = t.u;
                t.b = __halves2bfloat162(h2, h3); ah[wB] = t.u;
                t.b = __halves2bfloat162(l0, l1); al[wA] = t.u;
                t.b = __halves2bfloat162(l2, l3); al[wB] = t.u;
            }
        }
        // ---- stage W (already interleaved in global; straight copy) ----
        {
            const uint4* wsrc = (const uint4*)(Wc + (size_t)s * 34816);
            uint4* wdst = (uint4*)(smem + SMW_HI);
#pragma unroll
            for (int i = 0; i < 17; ++i)
                wdst[i * 256 + tid] = __ldg(&wsrc[i * 256 + tid]);
        }
        __syncthreads();

        // ---- 3 passes: (Ah,Wh), (Al,Wh), (Ah,Wl) ----
#pragma unroll
        for (int pass = 0; pass < 3; ++pass) {
            const char* abase = smem + ((pass == 1) ? SMA_LO : SMA_HI);
            const char* wbase = smem + ((pass == 2) ? SMW_LO : SMW_HI);
            const char* arow0 = abase + (wm * 32 + (lane >> 2)) * APITCH + (lane & 3) * 8;
            const char* brow0 = wbase + (wn * 64 + (lane >> 2)) * APITCH + (lane & 3) * 8;
#pragma unroll
            for (int g = 0; g < 8; ++g) {
                const int go = g * 32;
                uint2 a0 = *(const uint2*)(arow0 + go);                    // rows +0..  (a0,a2)
                uint2 a1 = *(const uint2*)(arow0 + 8 * APITCH + go);       // rows +8    (a1,a3)
                uint2 a2 = *(const uint2*)(arow0 + 16 * APITCH + go);      // m-tile 1
                uint2 a3 = *(const uint2*)(arow0 + 24 * APITCH + go);
                uint2 b[8];
#pragma unroll
                for (int j = 0; j < 8; ++j)
                    b[j] = *(const uint2*)(brow0 + j * 8 * APITCH + go);
#pragma unroll
                for (int j = 0; j < 8; ++j) {
                    mma_bf16(acc[0][j][0], acc[0][j][1], acc[0][j][2], acc[0][j][3],
                             a0.x, a1.x, a0.y, a1.y, b[j].x, b[j].y);
                    mma_bf16(acc[1][j][0], acc[1][j][1], acc[1][j][2], acc[1][j][3],
                             a2.x, a3.x, a2.y, a3.y, b[j].x, b[j].y);
                }
            }
        }
    }

    // ---- epilogue ----
#pragma unroll
    for (int i = 0; i < 2; ++i) {
        int r0 = row0 + wm * 32 + i * 16 + (lane >> 2);
#pragma unroll
        for (int j = 0; j < 8; ++j) {
            int col = wn * 64 + j * 8 + (lane & 3) * 2;
            float2 bv = __ldg((const float2*)&bias[col]);
            float2 o0 = make_float2(acc[i][j][0] + bv.x, acc[i][j][1] + bv.y);
            float2 o1 = make_float2(acc[i][j][2] + bv.x, acc[i][j][3] + bv.y);
            if (relu) {
                o0.x = fmaxf(o0.x, 0.f); o0.y = fmaxf(o0.y, 0.f);
                o1.x = fmaxf(o1.x, 0.f); o1.y = fmaxf(o1.y, 0.f);
            }
            if (r0 < n)     *(float2*)&OUT[(size_t)r0 * FDIM + col]       = o0;
            if (r0 + 8 < n) *(float2*)&OUT[(size_t)(r0 + 8) * FDIM + col] = o1;
        }
    }
}

// ================= pooling + classifier =================
__global__ void cnt_kernel(const int* __restrict__ batch, int n) {
    int i = blockIdx.x * blockDim.x + threadIdx.x;
    if (i < n) atomicAdd(&g_cnt[batch[i]], 1.0f);
}
__global__ void pool_kernel(const float4* __restrict__ H, const int* __restrict__ batch, int n) {
    int idx = blockIdx.x * blockDim.x + threadIdx.x;
    if (idx >= n * 32) return;
    int row = idx >> 5;
    int c   = idx & 31;
    int g   = batch[row];
    float4 v = __ldg(&H[(long)row * 32 + c]);
    float4* p = (float4*)&g_sums[g * FDIM + c * 4];
    asm volatile("red.global.add.v4.f32 [%0], {%1,%2,%3,%4};"
                 :: "l"(p), "f"(v.x), "f"(v.y), "f"(v.z), "f"(v.w) : "memory");
}
__global__ void final_kernel(const float* __restrict__ Wl, const float* __restrict__ bl,
                             float* __restrict__ out, int ngraphs) {
    int tid = blockIdx.x * blockDim.x + threadIdx.x;
    if (tid >= ngraphs * CLS) return;
    int g = tid / CLS;
    int c = tid % CLS;
    float s = 0.0f;
    const float* sp = &g_sums[g * FDIM];
#pragma unroll 16
    for (int d = 0; d < FDIM; ++d) s = fmaf(sp[d], Wl[d * CLS + c], s);
    float cnt = fmaxf(g_cnt[g], 1.0f);
    out[g * CLS + c] = s / cnt + bl[c];
}

// ---------------------------------------------------------------
extern "C" void kernel_launch(void* const* d_in, const int* in_sizes, int n_in,
                              void* d_out, int out_size) {
    const float* x   = (const float*)d_in[0];
    const int*   ei  = (const int*)  d_in[1];
    const int*   bat = (const int*)  d_in[2];
    const float* W1  = (const float*)d_in[3];
    const float* b1  = (const float*)d_in[4];
    const float* W2  = (const float*)d_in[5];
    const float* b2  = (const float*)d_in[6];
    const float* W3  = (const float*)d_in[7];
    const float* b3  = (const float*)d_in[8];
    const float* Wl  = (const float*)d_in[9];
    const float* bl  = (const float*)d_in[10];
    float* out = (float*)d_out;

    const int n = in_sizes[0] / FDIM;          // 100000
    const int E = in_sizes[1] / 2;             // 1600000
    const int G = out_size / CLS;              // 64
    const int* src = ei;
    const int* dst = ei + E;
    const int ntiles = (n + 127) / 128;

    float *deg, *T1, *T2, *H1, *H2, *H3, *sums, *cnt;
    int *rcnt, *fill;
    __nv_bfloat16* Wc;
    cudaGetSymbolAddress((void**)&deg,  g_deg);
    cudaGetSymbolAddress((void**)&rcnt, g_rcnt);
    cudaGetSymbolAddress((void**)&fill, g_fill);
    cudaGetSymbolAddress((void**)&T1,   g_T1);
    cudaGetSymbolAddress((void**)&T2,   g_T2);
    cudaGetSymbolAddress((void**)&H1,   g_H1);
    cudaGetSymbolAddress((void**)&H2,   g_H2);
    cudaGetSymbolAddress((void**)&H3,   g_H3);
    cudaGetSymbolAddress((void**)&sums, g_sums);
    cudaGetSymbolAddress((void**)&cnt,  g_cnt);
    cudaGetSymbolAddress((void**)&Wc,   g_Wc);

    cudaFuncSetAttribute(gemm_mma_kernel, cudaFuncAttributeMaxDynamicSharedMemorySize, SM_GEMM);

    const int TB = 256;

    // degree / normalization
    cudaMemsetAsync(deg, 0, (size_t)n * sizeof(float));
    deg_kernel <<<(E + TB - 1) / TB, TB>>>(src, E);
    dinv_kernel<<<(n + TB - 1) / TB, TB>>>(n);

    // CSR build (by dst)
    cudaMemsetAsync(rcnt, 0, (size_t)n * sizeof(int));
    cudaMemsetAsync(fill, 0, (size_t)n * sizeof(int));
    rcnt_kernel<<<(E + TB - 1) / TB, TB>>>(dst, E);
    const int nb = (n + SCAN_B - 1) / SCAN_B;
    scan1_kernel<<<nb, SCAN_B>>>(n);
    scan2_kernel<<<1, 256>>>(nb);
    scan3_kernel<<<(n + TB - 1) / TB, TB>>>(n);
    fill_kernel<<<(E + TB - 1) / TB, TB>>>(src, dst, E);

    // weight pre-conversion
    const int wblk = (3 * 16384 + TB - 1) / TB;
    wcvt_kernel<<<wblk, TB>>>(W1, Wc);
    wcvt_kernel<<<wblk, TB>>>(W2, Wc + (size_t)3 * 34816);
    wcvt_kernel<<<wblk, TB>>>(W3, Wc + (size_t)6 * 34816);

    const int propBlocks = (n * 32 + TB - 1) / TB;

    struct Layer { const float* X; const float* b; float* O; int relu; int widx; };
    Layer layers[3] = {
        { x,  b1, H1, 1, 0 },
        { H1, b2, H2, 1, 1 },
        { H2, b3, H3, 0, 2 },
    };

    for (int l = 0; l < 3; ++l) {
        const float* X = layers[l].X;
        prop_csr_kernel<0><<<propBlocks, TB>>>((const float4*)X, nullptr, (float4*)T1, n);
        prop_csr_kernel<1><<<propBlocks, TB>>>((const float4*)T1, (const float4*)X, (float4*)T2, n);
        gemm_mma_kernel<<<ntiles, 256, SM_GEMM>>>(X, T1, T2,
                                                  Wc + (size_t)layers[l].widx * 3 * 34816,
                                                  layers[l].b, layers[l].O, n, layers[l].relu);
    }

    // mean pool + classifier
    cudaMemsetAsync(sums, 0, (size_t)G * FDIM * sizeof(float));
    cudaMemsetAsync(cnt,  0, (size_t)G * sizeof(float));
    cnt_kernel <<<(n + TB - 1) / TB, TB>>>(bat, n);
    pool_kernel<<<(n * 32 + TB - 1) / TB, TB>>>((const float4*)H3, bat, n);
    final_kernel<<<(G * CLS + TB - 1) / TB, TB>>>(Wl, bl, out, G);
}